// round 9
// baseline (speedup 1.0000x reference)
#include <cuda_runtime.h>
#include <cuda_bf16.h>
#include <math.h>

#define NCTA 128

// Scratch (device globals: allowed; no runtime allocation)
__device__ float g_dct[1024 * 64];     // block-major: [block][coef]
__device__ float g_spatial[1024];      // per-block sigmoid spatial gate
__device__ float g_sqpart[NCTA][64];   // per-CTA partial sums of each coefficient
__device__ float g_out2d[256 * 256];   // final 2D map before broadcast

// ---------------------------------------------------------------------------
// Kernel 1: 8x8 DCT (8 threads per block) + spatial gate + coefficient partials
// grid = 128 CTAs x 64 threads; thread -> (block b, column j); 8 blocks/CTA
// ---------------------------------------------------------------------------
__global__ void __launch_bounds__(64)
k_dct(const float* __restrict__ x,
      const float* __restrict__ sse_w,
      const float* __restrict__ sse_b)
{
    __shared__ float sD[64];
    __shared__ float red[2][64];
    int tid = threadIdx.x;             // 0..63
    int w = tid >> 5, lane = tid & 31;

    {
        int k = tid >> 3, n = tid & 7;
        float v = 0.5f * cospif((float)((2 * n + 1) * k) / 16.0f);
        if (k == 0) v = 0.35355339059327373f;  // 1/(2*sqrt(2))
        sD[tid] = v;
    }
    __syncthreads();

    int g = blockIdx.x * 64 + tid;
    int b = g >> 3;                    // block id 0..1023
    int j = g & 7;                     // column within 8x8 block
    int R = b >> 5, C = b & 31;
    int baseLane = lane & 24;          // this block's 8-lane group in the warp

    // Load column j of the 8x8 block from channel 0 (stride 3)
    float a[8];
    const float* base = x + ((size_t)(R * 8) * 256 + C * 8 + j) * 3;
#pragma unroll
    for (int k = 0; k < 8; k++)
        a[k] = base[k * 256 * 3];

    // Row pass (thread-local): t[i] = sum_k D[i][k] * a[k]
    float t[8];
#pragma unroll
    for (int i = 0; i < 8; i++) {
        float s = 0.f;
#pragma unroll
        for (int k = 0; k < 8; k++) s += sD[i * 8 + k] * a[k];
        t[i] = s;
    }

    // Column pass via shuffles: d[i] = dct[i][j] = sum_l t[i][l] * D[j][l]
    float d[8];
    float sp = 0.f;
#pragma unroll
    for (int i = 0; i < 8; i++) {
        float s = 0.f;
#pragma unroll
        for (int l = 0; l < 8; l++) {
            float tl = __shfl_sync(0xffffffffu, t[i], baseLane + l);
            s += tl * sD[j * 8 + l];
        }
        d[i] = s;
        g_dct[b * 64 + i * 8 + j] = s;
        sp += sse_w[i * 8 + j] * s;
    }

    // Spatial gate: reduce sp over the 8 lanes of this block
    sp += __shfl_xor_sync(0xffffffffu, sp, 1);
    sp += __shfl_xor_sync(0xffffffffu, sp, 2);
    sp += __shfl_xor_sync(0xffffffffu, sp, 4);
    if (j == 0) g_spatial[b] = 1.f / (1.f + expf(-(sp + sse_b[0])));

    // Coefficient partial sums over the 4 blocks in this warp (xor 8, 16)
#pragma unroll
    for (int i = 0; i < 8; i++) {
        float v = d[i];
        v += __shfl_xor_sync(0xffffffffu, v, 8);
        v += __shfl_xor_sync(0xffffffffu, v, 16);
        if (lane < 8) red[w][i * 8 + lane] = v;
    }
    __syncthreads();
    g_sqpart[blockIdx.x][tid] = red[0][tid] + red[1][tid];
}

// ---------------------------------------------------------------------------
// Kernel 2: tiny MLP (redundant per CTA) + gate + 8x8 IDCT -> g_out2d (256 KB)
// grid = 128 CTAs x 64 threads; thread -> (block b, column j); 8 blocks/CTA
// ---------------------------------------------------------------------------
__global__ void __launch_bounds__(64)
k_mlp_idct(const float* __restrict__ fc1_w,
           const float* __restrict__ fc1_b,
           const float* __restrict__ fc2_w,
           const float* __restrict__ fc2_b)
{
    __shared__ float sD[64], s_sq[64], s_h[32], s_sc[64];
    int tid = threadIdx.x;
    int lane = tid & 31;

    {
        int k = tid >> 3, n = tid & 7;
        float v = 0.5f * cospif((float)((2 * n + 1) * k) / 16.0f);
        if (k == 0) v = 0.35355339059327373f;
        sD[tid] = v;
        float s = 0.f;
#pragma unroll
        for (int p = 0; p < NCTA; p++) s += g_sqpart[p][tid];
        s_sq[tid] = s * (1.0f / 1024.0f);
    }
    __syncthreads();

    // h = relu(fc1_w @ sq + fc1_b), 32 outputs
    if (tid < 32) {
        float s = fc1_b[tid];
#pragma unroll
        for (int c = 0; c < 64; c++) s += fc1_w[tid * 64 + c] * s_sq[c];
        s_h[tid] = fmaxf(s, 0.f);
    }
    __syncthreads();

    // scale_c = sigmoid(fc2_w @ h + fc2_b), 64 outputs
    {
        float s = fc2_b[tid];
#pragma unroll
        for (int r = 0; r < 32; r++) s += fc2_w[tid * 32 + r] * s_h[r];
        s_sc[tid] = 1.f / (1.f + expf(-s));
    }
    __syncthreads();

    int g = blockIdx.x * 64 + tid;
    int b = g >> 3;
    int j = g & 7;
    int R = b >> 5, C = b & 31;
    int baseLane = lane & 24;

    float sp = g_spatial[b];

    // Gate: y = dct * (dct >= 0 ? max(sc, sp) : min(sc, sp))
    float y[8];
#pragma unroll
    for (int i = 0; i < 8; i++) {
        float v = g_dct[b * 64 + i * 8 + j];
        float sc = s_sc[i * 8 + j];
        float m = (v >= 0.f) ? fmaxf(sc, sp) : fminf(sc, sp);
        y[i] = v * m;
    }

    // Row pass: u[i] = sum_k D[k][i] * y[k]   (D^T @ Y)
    float u[8];
#pragma unroll
    for (int i = 0; i < 8; i++) {
        float s = 0.f;
#pragma unroll
        for (int k = 0; k < 8; k++) s += sD[k * 8 + i] * y[k];
        u[i] = s;
    }

    // Column pass via shuffles; coalesced stores per warp-row
#pragma unroll
    for (int i = 0; i < 8; i++) {
        float s = 0.f;
#pragma unroll
        for (int l = 0; l < 8; l++) {
            float ul = __shfl_sync(0xffffffffu, u[i], baseLane + l);
            s += ul * sD[l * 8 + j];
        }
        g_out2d[(R * 8 + i) * 256 + C * 8 + j] = s;
    }
}

// ---------------------------------------------------------------------------
// Kernel 3: broadcast out2d (256 KB) to all planes of d_out (write-bound)
// grid = (64, planes/16) x 256 threads; 1 L2 read per 16 plane stores
// ---------------------------------------------------------------------------
__global__ void __launch_bounds__(256)
k_bcast(float4* __restrict__ out)
{
    int q = blockIdx.x * 256 + threadIdx.x;         // float4 index within plane
    const float4* src = (const float4*)g_out2d;
    float4 v = src[q];
    size_t base = (size_t)(blockIdx.y * 16) * 16384 + q;
#pragma unroll
    for (int pp = 0; pp < 16; pp++)
        out[base + (size_t)pp * 16384] = v;
}

__global__ void __launch_bounds__(256)
k_bcast_guard(float4* __restrict__ out, int planes)
{
    int q = blockIdx.x * 256 + threadIdx.x;
    const float4* src = (const float4*)g_out2d;
    float4 v = src[q];
    int p0 = blockIdx.y * 16;
#pragma unroll
    for (int pp = 0; pp < 16; pp++) {
        int p = p0 + pp;
        if (p < planes) out[(size_t)p * 16384 + q] = v;
    }
}

extern "C" void kernel_launch(void* const* d_in, const int* in_sizes, int n_in,
                              void* d_out, int out_size)
{
    const float* x      = (const float*)d_in[0];
    const float* fc1_w  = (const float*)d_in[1];
    const float* fc1_b  = (const float*)d_in[2];
    const float* fc2_w  = (const float*)d_in[3];
    const float* fc2_b  = (const float*)d_in[4];
    const float* sse_w  = (const float*)d_in[5];
    const float* sse_b  = (const float*)d_in[6];
    // d_in[7] = bs (unused; plane count derived from out_size)

    int planes = out_size / (256 * 256);   // 64*3 = 192

    k_dct<<<NCTA, 64>>>(x, sse_w, sse_b);
    k_mlp_idct<<<NCTA, 64>>>(fc1_w, fc1_b, fc2_w, fc2_b);

    if ((planes & 15) == 0) {
        dim3 grid(64, planes / 16);
        k_bcast<<<grid, 256>>>((float4*)d_out);
    } else {
        dim3 grid(64, (planes + 15) / 16);
        k_bcast_guard<<<grid, 256>>>((float4*)d_out, planes);
    }
}